// round 6
// baseline (speedup 1.0000x reference)
#include <cuda_runtime.h>
#include <math.h>

// DiffJPEG forward: fused kernel. Quad-per-block DCT path, direct global loads,
// row-IDCT merged into the output phase.
// img: (16,3,512,512) f32, quality: int scalar, out: (16,3,512,512) f32.

#define IMG_W 512
#define IMG_H 512
#define BATCH 16
#define NTHREADS 768
#define NUNITS 192                        // 3 ch * 64 blocks per 8-row strip
// smem slot: addr(unit,a,b) = unit*72 + (a>>2)*36 + (a&3)*8 + b
#define SMEM_FLOATS (NUNITS * 72)         // 13824
#define SMEM_BYTES  (SMEM_FLOATS * 4)     // 55296 (dynamic)

#define MAGIC 12582912.0f                 // 1.5 * 2^23: round-to-nearest-even

// Orthonormal 8-pt DCT-II butterfly constants (double-derived)
#define CA  0.35355339059327373f
#define CB1 0.46193976625564337f
#define CB3 0.19134171618254492f
#define CD1 0.49039264020161522f
#define CD3 0.41573480615127262f
#define CD5 0.27778511650980114f
#define CD7 0.09754516100806413f

#define FDCT8(x0,x1,x2,x3,x4,x5,x6,x7) do {                                  \
    float e0=(x0)+(x7), e1=(x1)+(x6), e2=(x2)+(x5), e3=(x3)+(x4);            \
    float o0=(x0)-(x7), o1=(x1)-(x6), o2=(x2)-(x5), o3=(x3)-(x4);            \
    float ee0=e0+e3, ee1=e1+e2, eo0=e0-e3, eo1=e1-e2;                        \
    (x0) = CA*(ee0+ee1);                                                     \
    (x4) = CA*(ee0-ee1);                                                     \
    (x2) = CB1*eo0 + CB3*eo1;                                                \
    (x6) = CB3*eo0 - CB1*eo1;                                                \
    (x1) = CD1*o0 + CD3*o1 + CD5*o2 + CD7*o3;                                \
    (x3) = CD3*o0 - CD7*o1 - CD1*o2 - CD5*o3;                                \
    (x5) = CD5*o0 - CD1*o1 + CD7*o2 + CD3*o3;                                \
    (x7) = CD7*o0 - CD5*o1 + CD3*o2 - CD1*o3;                                \
} while(0)

#define IDCT8(x0,x1,x2,x3,x4,x5,x6,x7) do {                                  \
    float ee0 = CA*((x0)+(x4)), ee1 = CA*((x0)-(x4));                        \
    float eo0 = CB1*(x2) + CB3*(x6), eo1 = CB3*(x2) - CB1*(x6);              \
    float o0 = CD1*(x1) + CD3*(x3) + CD5*(x5) + CD7*(x7);                    \
    float o1 = CD3*(x1) - CD7*(x3) - CD1*(x5) - CD5*(x7);                    \
    float o2 = CD5*(x1) - CD1*(x3) + CD7*(x5) + CD3*(x7);                    \
    float o3 = CD7*(x1) - CD5*(x3) + CD3*(x5) - CD1*(x7);                    \
    float e0=ee0+eo0, e3=ee0-eo0, e1=ee1+eo1, e2=ee1-eo1;                    \
    (x0)=e0+o0; (x7)=e0-o0; (x1)=e1+o1; (x6)=e1-o1;                          \
    (x2)=e2+o2; (x5)=e2-o2; (x3)=e3+o3; (x4)=e3-o3;                          \
} while(0)

__constant__ float c_lum[64] = {
    16, 11, 10, 16, 24, 40, 51, 61,
    12, 12, 14, 19, 26, 58, 60, 55,
    14, 13, 16, 24, 40, 57, 69, 56,
    14, 17, 22, 29, 51, 87, 80, 62,
    18, 22, 37, 56, 68, 109, 103, 77,
    24, 35, 55, 64, 81, 104, 113, 92,
    49, 64, 78, 87, 103, 121, 120, 101,
    72, 92, 95, 98, 112, 100, 103, 99
};
__constant__ float c_chrom[64] = {
    17, 18, 24, 47, 99, 99, 99, 99,
    18, 21, 26, 66, 99, 99, 99, 99,
    24, 26, 56, 99, 99, 99, 99, 99,
    47, 66, 99, 99, 99, 99, 99, 99,
    99, 99, 99, 99, 99, 99, 99, 99,
    99, 99, 99, 99, 99, 99, 99, 99,
    99, 99, 99, 99, 99, 99, 99, 99,
    99, 99, 99, 99, 99, 99, 99, 99
};

__global__ void __launch_bounds__(NTHREADS)
jpeg_kernel(const float* __restrict__ img,
            const int* __restrict__ quality,
            float* __restrict__ out)
{
    extern __shared__ float sm[];
    __shared__ float2 qs2[128];   // (q, 1/q): [0:64) lum, [64:128) chrom

    const int tid = threadIdx.x;

    if (tid < 128) {
        int q = *quality;
        q = max(1, min(100, q));
        float scale = (q < 50) ? (5000.0f / (float)q) : (200.0f - 2.0f * (float)q);
        float base = (tid < 64) ? c_lum[tid] : c_chrom[tid - 64];
        float v = (base * scale + 50.0f) / 100.0f;
        v = fminf(fmaxf(v, 1.0f), 255.0f);
        qs2[tid] = make_float2(v, 1.0f / v);
    }
    __syncthreads();   // qs2 visible to all warps

    const int b = blockIdx.x >> 6;
    const int strip = blockIdx.x & 63;
    const int row0 = strip * 8;
    const size_t CH = (size_t)IMG_H * IMG_W;
    const size_t img_base = (size_t)b * 3 * CH;

    // ---- Phase B: quad per (channel, 8x8 block); direct global load ----
    {
        const int unit = tid >> 2;          // 0..191 = c*64 + blk
        const int q = tid & 3;              // row-pair index
        const int c = unit >> 6;            // channel, uniform per warp
        const int blk = unit & 63;
        float* ub = sm + unit * 72;

        // load my 2 rows x 8 cols of R,G,B; convert to my channel (x255 folded)
        float x[2][8];
        #pragma unroll
        for (int i = 0; i < 2; i++) {
            size_t off = img_base + (size_t)(row0 + 2 * q + i) * IMG_W + blk * 8;
            #pragma unroll
            for (int h = 0; h < 2; h++) {
                float4 r4 = *(const float4*)(img + off + 4 * h);
                float4 g4 = *(const float4*)(img + off + 4 * h + CH);
                float4 b4 = *(const float4*)(img + off + 4 * h + 2 * CH);
                const float* Rp = &r4.x; const float* Gp = &g4.x; const float* Bp = &b4.x;
                #pragma unroll
                for (int j = 0; j < 4; j++) {
                    float R = Rp[j], G = Gp[j], B = Bp[j];
                    float v;
                    if (c == 0)
                        v = fmaf(76.245f, R, fmaf(149.685f, G, 29.07f * B));
                    else if (c == 1)
                        v = fmaf(-43.0185f, R, fmaf(-84.4815f, G, fmaf(127.5f, B, 128.0f)));
                    else
                        v = fmaf(127.5f, R, fmaf(-106.7685f, G, fmaf(-20.7315f, B, 128.0f)));
                    x[i][4 * h + j] = v;
                }
            }
        }

        // row forward DCT on my 2 rows
        #pragma unroll
        for (int i = 0; i < 2; i++)
            FDCT8(x[i][0],x[i][1],x[i][2],x[i][3],x[i][4],x[i][5],x[i][6],x[i][7]);

        // transpose store T1[l][r]: my r's (2q,2q+1) are one float2
        #pragma unroll
        for (int l = 0; l < 8; l++) {
            *(float2*)(ub + (l >> 2) * 36 + (l & 3) * 8 + 2 * q)
                = make_float2(x[0][l], x[1][l]);
        }
        __syncwarp();

        // load T1 rows l = 2q, 2q+1 (contiguous over r)
        float y[2][8];
        #pragma unroll
        for (int j = 0; j < 2; j++) {
            int l = 2 * q + j;
            float* rp = ub + (l >> 2) * 36 + (l & 3) * 8;
            float4 v0 = *(const float4*)(rp);
            float4 v1 = *(const float4*)(rp + 4);
            y[j][0]=v0.x; y[j][1]=v0.y; y[j][2]=v0.z; y[j][3]=v0.w;
            y[j][4]=v1.x; y[j][5]=v1.y; y[j][6]=v1.z; y[j][7]=v1.w;
        }
        // column forward DCT -> y[j][k] = D[k][2q+j]
        #pragma unroll
        for (int j = 0; j < 2; j++)
            FDCT8(y[j][0],y[j][1],y[j][2],y[j][3],y[j][4],y[j][5],y[j][6],y[j][7]);

        // -128 input shift commutes to DC only (owner: q=0, j=0, k=0)
        if (q == 0) y[0][0] -= 1024.0f;

        // quantize: reciprocal multiply + magic round-to-even (exact rint)
        const float2* qt = ((b * 3 + c) < BATCH) ? qs2 : (qs2 + 64);
        #pragma unroll
        for (int j = 0; j < 2; j++) {
            int l = 2 * q + j;
            #pragma unroll
            for (int k = 0; k < 8; k++) {
                float2 qv = qt[k * 8 + l];
                float t = y[j][k] * qv.y;
                t = __fadd_rn(__fadd_rn(t, MAGIC), -MAGIC);
                y[j][k] = t * qv.x;
            }
        }

        // +128 output shift commutes to DC
        if (q == 0) y[0][0] += 1024.0f;

        // column inverse DCT -> y[j][i] = T2[i][2q+j]
        #pragma unroll
        for (int j = 0; j < 2; j++)
            IDCT8(y[j][0],y[j][1],y[j][2],y[j][3],y[j][4],y[j][5],y[j][6],y[j][7]);

        __syncwarp();   // all quad lanes done reading T1 before overwriting
        // store T2[i][l]: my l's (2q,2q+1) are one float2 per row i
        #pragma unroll
        for (int i = 0; i < 8; i++) {
            *(float2*)(ub + (i >> 2) * 36 + (i & 3) * 8 + 2 * q)
                = make_float2(y[0][i], y[1][i]);
        }
    }
    __syncthreads();

    // ---- Phase C: one thread per spatial (block, row): row-IDCT x3 channels,
    //      color convert, clipped RGB store ----
    if (tid < 512) {
        const int row = tid >> 6;          // 0..7 (same row across a warp)
        const int blk = tid & 63;          // consecutive lanes -> consecutive blocks
        const int ro = (row >> 2) * 36 + (row & 3) * 8;

        float Y[8], Cb[8], Cr[8];
        {
            float* py = sm + blk * 72 + ro;
            float* pb = sm + (64 + blk) * 72 + ro;
            float* pr = sm + (128 + blk) * 72 + ro;
            float4 a, d;
            a = *(const float4*)(py);  d = *(const float4*)(py + 4);
            Y[0]=a.x; Y[1]=a.y; Y[2]=a.z; Y[3]=a.w; Y[4]=d.x; Y[5]=d.y; Y[6]=d.z; Y[7]=d.w;
            a = *(const float4*)(pb);  d = *(const float4*)(pb + 4);
            Cb[0]=a.x; Cb[1]=a.y; Cb[2]=a.z; Cb[3]=a.w; Cb[4]=d.x; Cb[5]=d.y; Cb[6]=d.z; Cb[7]=d.w;
            a = *(const float4*)(pr);  d = *(const float4*)(pr + 4);
            Cr[0]=a.x; Cr[1]=a.y; Cr[2]=a.z; Cr[3]=a.w; Cr[4]=d.x; Cr[5]=d.y; Cr[6]=d.z; Cr[7]=d.w;
        }

        // row inverse DCT per channel
        IDCT8(Y[0],Y[1],Y[2],Y[3],Y[4],Y[5],Y[6],Y[7]);
        IDCT8(Cb[0],Cb[1],Cb[2],Cb[3],Cb[4],Cb[5],Cb[6],Cb[7]);
        IDCT8(Cr[0],Cr[1],Cr[2],Cr[3],Cr[4],Cr[5],Cr[6],Cr[7]);

        // YCbCr -> RGB, clip, pack
        float R[8], G[8], B[8];
        #pragma unroll
        for (int j = 0; j < 8; j++) {
            float y  = Y[j];
            float cb = Cb[j] - 128.0f;
            float cr = Cr[j] - 128.0f;
            float rr = y + 1.402f * cr;
            float gg = y - 0.34414f * cb - 0.71414f * cr;
            float bb = y + 1.772f * cb;
            R[j] = fminf(fmaxf(rr * (1.0f / 255.0f), 0.0f), 1.0f);
            G[j] = fminf(fmaxf(gg * (1.0f / 255.0f), 0.0f), 1.0f);
            B[j] = fminf(fmaxf(bb * (1.0f / 255.0f), 0.0f), 1.0f);
        }

        size_t off = img_base + (size_t)(row0 + row) * IMG_W + blk * 8;
        *(float4*)(out + off)              = make_float4(R[0],R[1],R[2],R[3]);
        *(float4*)(out + off + 4)          = make_float4(R[4],R[5],R[6],R[7]);
        *(float4*)(out + off + CH)         = make_float4(G[0],G[1],G[2],G[3]);
        *(float4*)(out + off + CH + 4)     = make_float4(G[4],G[5],G[6],G[7]);
        *(float4*)(out + off + 2*CH)       = make_float4(B[0],B[1],B[2],B[3]);
        *(float4*)(out + off + 2*CH + 4)   = make_float4(B[4],B[5],B[6],B[7]);
    }
}

extern "C" void kernel_launch(void* const* d_in, const int* in_sizes, int n_in,
                              void* d_out, int out_size)
{
    const float* img = (const float*)d_in[0];
    const int* quality = (const int*)d_in[1];
    float* out = (float*)d_out;

    cudaFuncSetAttribute(jpeg_kernel,
                         cudaFuncAttributeMaxDynamicSharedMemorySize,
                         SMEM_BYTES);

    dim3 grid(BATCH * (IMG_H / 8));  // 1024 CTAs
    jpeg_kernel<<<grid, NTHREADS, SMEM_BYTES>>>(img, quality, out);
}

// round 7
// speedup vs baseline: 1.2981x; 1.2981x over previous
#include <cuda_runtime.h>
#include <math.h>

// DiffJPEG forward: fused kernel. Smem color convert (Phase A), quad-per-block
// DCT/quant (Phase B, ends at T2), row-IDCT + color-out merged in Phase C.
// img: (16,3,512,512) f32, quality: int scalar, out: (16,3,512,512) f32.

#define IMG_W 512
#define IMG_H 512
#define BATCH 16
#define NTHREADS 768
#define NUNITS 192                        // 3 ch * 64 blocks per 8-row strip
// smem slot: addr(unit,a,b) = unit*72 + (a>>2)*36 + (a&3)*8 + b
#define SMEM_FLOATS (NUNITS * 72)         // 13824
#define SMEM_BYTES  (SMEM_FLOATS * 4)     // 55296 (dynamic)

#define MAGIC 12582912.0f                 // 1.5 * 2^23: round-to-nearest-even

// Orthonormal 8-pt DCT-II butterfly constants (double-derived)
#define CA  0.35355339059327373f
#define CB1 0.46193976625564337f
#define CB3 0.19134171618254492f
#define CD1 0.49039264020161522f
#define CD3 0.41573480615127262f
#define CD5 0.27778511650980114f
#define CD7 0.09754516100806413f

#define FDCT8(x0,x1,x2,x3,x4,x5,x6,x7) do {                                  \
    float e0=(x0)+(x7), e1=(x1)+(x6), e2=(x2)+(x5), e3=(x3)+(x4);            \
    float o0=(x0)-(x7), o1=(x1)-(x6), o2=(x2)-(x5), o3=(x3)-(x4);            \
    float ee0=e0+e3, ee1=e1+e2, eo0=e0-e3, eo1=e1-e2;                        \
    (x0) = CA*(ee0+ee1);                                                     \
    (x4) = CA*(ee0-ee1);                                                     \
    (x2) = CB1*eo0 + CB3*eo1;                                                \
    (x6) = CB3*eo0 - CB1*eo1;                                                \
    (x1) = CD1*o0 + CD3*o1 + CD5*o2 + CD7*o3;                                \
    (x3) = CD3*o0 - CD7*o1 - CD1*o2 - CD5*o3;                                \
    (x5) = CD5*o0 - CD1*o1 + CD7*o2 + CD3*o3;                                \
    (x7) = CD7*o0 - CD5*o1 + CD3*o2 - CD1*o3;                                \
} while(0)

#define IDCT8(x0,x1,x2,x3,x4,x5,x6,x7) do {                                  \
    float ee0 = CA*((x0)+(x4)), ee1 = CA*((x0)-(x4));                        \
    float eo0 = CB1*(x2) + CB3*(x6), eo1 = CB3*(x2) - CB1*(x6);              \
    float o0 = CD1*(x1) + CD3*(x3) + CD5*(x5) + CD7*(x7);                    \
    float o1 = CD3*(x1) - CD7*(x3) - CD1*(x5) - CD5*(x7);                    \
    float o2 = CD5*(x1) - CD1*(x3) + CD7*(x5) + CD3*(x7);                    \
    float o3 = CD7*(x1) - CD5*(x3) + CD3*(x5) - CD1*(x7);                    \
    float e0=ee0+eo0, e3=ee0-eo0, e1=ee1+eo1, e2=ee1-eo1;                    \
    (x0)=e0+o0; (x7)=e0-o0; (x1)=e1+o1; (x6)=e1-o1;                          \
    (x2)=e2+o2; (x5)=e2-o2; (x3)=e3+o3; (x4)=e3-o3;                          \
} while(0)

__constant__ float c_lum[64] = {
    16, 11, 10, 16, 24, 40, 51, 61,
    12, 12, 14, 19, 26, 58, 60, 55,
    14, 13, 16, 24, 40, 57, 69, 56,
    14, 17, 22, 29, 51, 87, 80, 62,
    18, 22, 37, 56, 68, 109, 103, 77,
    24, 35, 55, 64, 81, 104, 113, 92,
    49, 64, 78, 87, 103, 121, 120, 101,
    72, 92, 95, 98, 112, 100, 103, 99
};
__constant__ float c_chrom[64] = {
    17, 18, 24, 47, 99, 99, 99, 99,
    18, 21, 26, 66, 99, 99, 99, 99,
    24, 26, 56, 99, 99, 99, 99, 99,
    47, 66, 99, 99, 99, 99, 99, 99,
    99, 99, 99, 99, 99, 99, 99, 99,
    99, 99, 99, 99, 99, 99, 99, 99,
    99, 99, 99, 99, 99, 99, 99, 99,
    99, 99, 99, 99, 99, 99, 99, 99
};

__global__ void __launch_bounds__(NTHREADS)
jpeg_kernel(const float* __restrict__ img,
            const int* __restrict__ quality,
            float* __restrict__ out)
{
    extern __shared__ float sm[];
    __shared__ float2 qs2[128];   // (q, 1/q): [0:64) lum, [64:128) chrom

    const int tid = threadIdx.x;

    if (tid < 128) {
        int q = *quality;
        q = max(1, min(100, q));
        float scale = (q < 50) ? (5000.0f / (float)q) : (200.0f - 2.0f * (float)q);
        float base = (tid < 64) ? c_lum[tid] : c_chrom[tid - 64];
        float v = (base * scale + 50.0f) / 100.0f;
        v = fminf(fmaxf(v, 1.0f), 255.0f);
        qs2[tid] = make_float2(v, 1.0f / v);
    }

    const int b = blockIdx.x >> 6;
    const int strip = blockIdx.x & 63;
    const int row0 = strip * 8;
    const size_t CH = (size_t)IMG_H * IMG_W;
    const size_t img_base = (size_t)b * 3 * CH;

    // ---- Phase A: load + RGB->YCbCr (x255 folded) into block-slot smem ----
    #pragma unroll
    for (int g = 0; g < 2; g++) {
        int idx = tid + g * NTHREADS;
        if (idx < 1024) {
            int r = idx >> 7;
            int col = (idx & 127) << 2;
            size_t off = img_base + (size_t)(row0 + r) * IMG_W + col;
            float4 r4 = *(const float4*)(img + off);
            float4 g4 = *(const float4*)(img + off + CH);
            float4 b4 = *(const float4*)(img + off + 2 * CH);
            float4 y4, cb4, cr4;
            {
                const float* Rp = &r4.x; const float* Gp = &g4.x; const float* Bp = &b4.x;
                float* Yp = &y4.x; float* Cbp = &cb4.x; float* Crp = &cr4.x;
                #pragma unroll
                for (int j = 0; j < 4; j++) {
                    float R = Rp[j], G = Gp[j], B = Bp[j];
                    Yp[j]  = fmaf(76.245f, R, fmaf(149.685f, G, 29.07f * B));
                    Cbp[j] = fmaf(-43.0185f, R, fmaf(-84.4815f, G, fmaf(127.5f, B, 128.0f)));
                    Crp[j] = fmaf(127.5f, R, fmaf(-106.7685f, G, fmaf(-20.7315f, B, 128.0f)));
                }
            }
            int blk = col >> 3;
            int sb = blk * 72 + (r >> 2) * 36 + (r & 3) * 8 + (col & 7);
            *(float4*)(sm + sb)             = y4;
            *(float4*)(sm + 64 * 72 + sb)   = cb4;
            *(float4*)(sm + 128 * 72 + sb)  = cr4;
        }
    }
    __syncthreads();

    // ---- Phase B: thread quad per 8x8 block; ends at T2 (transposed) ----
    {
        const int unit = tid >> 2;          // 0..191 (c*64 + blk)
        const int q = tid & 3;              // row-pair index
        const int c = unit >> 6;
        float* ub = sm + unit * 72;

        float x[2][8];
        // load my 2 spatial rows (a = 2q, 2q+1)
        #pragma unroll
        for (int i = 0; i < 2; i++) {
            int a = 2 * q + i;
            float* rp = ub + (a >> 2) * 36 + (a & 3) * 8;
            float4 v0 = *(const float4*)(rp);
            float4 v1 = *(const float4*)(rp + 4);
            x[i][0]=v0.x; x[i][1]=v0.y; x[i][2]=v0.z; x[i][3]=v0.w;
            x[i][4]=v1.x; x[i][5]=v1.y; x[i][6]=v1.z; x[i][7]=v1.w;
        }
        // row forward DCT
        #pragma unroll
        for (int i = 0; i < 2; i++)
            FDCT8(x[i][0],x[i][1],x[i][2],x[i][3],x[i][4],x[i][5],x[i][6],x[i][7]);

        __syncwarp();
        // transpose store T1[l][r]: my r's (2q,2q+1) are one float2
        #pragma unroll
        for (int l = 0; l < 8; l++) {
            *(float2*)(ub + (l >> 2) * 36 + (l & 3) * 8 + 2 * q)
                = make_float2(x[0][l], x[1][l]);
        }
        __syncwarp();

        // load my 2 transposed rows (cols l = 2q, 2q+1), contiguous over r
        float y[2][8];
        #pragma unroll
        for (int j = 0; j < 2; j++) {
            int l = 2 * q + j;
            float* rp = ub + (l >> 2) * 36 + (l & 3) * 8;
            float4 v0 = *(const float4*)(rp);
            float4 v1 = *(const float4*)(rp + 4);
            y[j][0]=v0.x; y[j][1]=v0.y; y[j][2]=v0.z; y[j][3]=v0.w;
            y[j][4]=v1.x; y[j][5]=v1.y; y[j][6]=v1.z; y[j][7]=v1.w;
        }
        // column forward DCT -> y[j][k] = D[k][2q+j]
        #pragma unroll
        for (int j = 0; j < 2; j++)
            FDCT8(y[j][0],y[j][1],y[j][2],y[j][3],y[j][4],y[j][5],y[j][6],y[j][7]);

        // -128 input shift commutes to DC only (owner: q=0, j=0, k=0)
        if (q == 0) y[0][0] -= 1024.0f;

        // quantize: reciprocal multiply + magic round-to-even (exact rint)
        const float2* qt = ((b * 3 + c) < BATCH) ? qs2 : (qs2 + 64);
        #pragma unroll
        for (int j = 0; j < 2; j++) {
            int l = 2 * q + j;
            #pragma unroll
            for (int k = 0; k < 8; k++) {
                float2 qv = qt[k * 8 + l];
                float t = y[j][k] * qv.y;
                t = __fadd_rn(__fadd_rn(t, MAGIC), -MAGIC);
                y[j][k] = t * qv.x;
            }
        }

        // +128 output shift commutes to DC
        if (q == 0) y[0][0] += 1024.0f;

        // column inverse DCT -> y[j][i] = T2[i][2q+j]
        #pragma unroll
        for (int j = 0; j < 2; j++)
            IDCT8(y[j][0],y[j][1],y[j][2],y[j][3],y[j][4],y[j][5],y[j][6],y[j][7]);

        __syncwarp();   // all quad lanes done reading T1 before overwriting
        // store T2[i][l]: my l's (2q,2q+1) are one float2 per row i
        #pragma unroll
        for (int i = 0; i < 8; i++) {
            *(float2*)(ub + (i >> 2) * 36 + (i & 3) * 8 + 2 * q)
                = make_float2(y[0][i], y[1][i]);
        }
    }
    __syncthreads();

    // ---- Phase C: one thread per spatial (block, row): row-IDCT x3 channels,
    //      color convert, clipped RGB store ----
    if (tid < 512) {
        const int row = tid >> 6;          // 0..7 (uniform per warp)
        const int blk = tid & 63;          // consecutive lanes -> consecutive blocks
        const int ro = (row >> 2) * 36 + (row & 3) * 8;

        float Y[8], Cb[8], Cr[8];
        {
            float* py = sm + blk * 72 + ro;
            float* pb = sm + (64 + blk) * 72 + ro;
            float* pr = sm + (128 + blk) * 72 + ro;
            float4 a, d;
            a = *(const float4*)(py);  d = *(const float4*)(py + 4);
            Y[0]=a.x; Y[1]=a.y; Y[2]=a.z; Y[3]=a.w; Y[4]=d.x; Y[5]=d.y; Y[6]=d.z; Y[7]=d.w;
            a = *(const float4*)(pb);  d = *(const float4*)(pb + 4);
            Cb[0]=a.x; Cb[1]=a.y; Cb[2]=a.z; Cb[3]=a.w; Cb[4]=d.x; Cb[5]=d.y; Cb[6]=d.z; Cb[7]=d.w;
            a = *(const float4*)(pr);  d = *(const float4*)(pr + 4);
            Cr[0]=a.x; Cr[1]=a.y; Cr[2]=a.z; Cr[3]=a.w; Cr[4]=d.x; Cr[5]=d.y; Cr[6]=d.z; Cr[7]=d.w;
        }

        // row inverse DCT per channel (T2 rows -> spatial pixels)
        IDCT8(Y[0],Y[1],Y[2],Y[3],Y[4],Y[5],Y[6],Y[7]);
        IDCT8(Cb[0],Cb[1],Cb[2],Cb[3],Cb[4],Cb[5],Cb[6],Cb[7]);
        IDCT8(Cr[0],Cr[1],Cr[2],Cr[3],Cr[4],Cr[5],Cr[6],Cr[7]);

        // YCbCr -> RGB, clip, store
        float R[8], G[8], B[8];
        #pragma unroll
        for (int j = 0; j < 8; j++) {
            float y  = Y[j];
            float cb = Cb[j] - 128.0f;
            float cr = Cr[j] - 128.0f;
            float rr = y + 1.402f * cr;
            float gg = y - 0.34414f * cb - 0.71414f * cr;
            float bb = y + 1.772f * cb;
            R[j] = fminf(fmaxf(rr * (1.0f / 255.0f), 0.0f), 1.0f);
            G[j] = fminf(fmaxf(gg * (1.0f / 255.0f), 0.0f), 1.0f);
            B[j] = fminf(fmaxf(bb * (1.0f / 255.0f), 0.0f), 1.0f);
        }

        size_t off = img_base + (size_t)(row0 + row) * IMG_W + blk * 8;
        *(float4*)(out + off)              = make_float4(R[0],R[1],R[2],R[3]);
        *(float4*)(out + off + 4)          = make_float4(R[4],R[5],R[6],R[7]);
        *(float4*)(out + off + CH)         = make_float4(G[0],G[1],G[2],G[3]);
        *(float4*)(out + off + CH + 4)     = make_float4(G[4],G[5],G[6],G[7]);
        *(float4*)(out + off + 2*CH)       = make_float4(B[0],B[1],B[2],B[3]);
        *(float4*)(out + off + 2*CH + 4)   = make_float4(B[4],B[5],B[6],B[7]);
    }
}

extern "C" void kernel_launch(void* const* d_in, const int* in_sizes, int n_in,
                              void* d_out, int out_size)
{
    const float* img = (const float*)d_in[0];
    const int* quality = (const int*)d_in[1];
    float* out = (float*)d_out;

    cudaFuncSetAttribute(jpeg_kernel,
                         cudaFuncAttributeMaxDynamicSharedMemorySize,
                         SMEM_BYTES);

    dim3 grid(BATCH * (IMG_H / 8));  // 1024 CTAs
    jpeg_kernel<<<grid, NTHREADS, SMEM_BYTES>>>(img, quality, out);
}

// round 8
// speedup vs baseline: 1.3846x; 1.0667x over previous
#include <cuda_runtime.h>
#include <math.h>

// DiffJPEG forward: fused kernel, thread-quad per 8x8 block (R4 structure),
// zipped quant tables (LDS.128) + fmaf magic rounding.
// img: (16,3,512,512) f32, quality: int scalar, out: (16,3,512,512) f32.

#define IMG_W 512
#define IMG_H 512
#define BATCH 16
#define NTHREADS 768
#define NUNITS 192                        // 3 ch * 64 blocks per 8-row strip
// smem slot: addr(unit,a,b) = unit*72 + (a>>2)*36 + (a&3)*8 + b
#define SMEM_FLOATS (NUNITS * 72)         // 13824
#define SMEM_BYTES  (SMEM_FLOATS * 4)     // 55296

#define MAGIC 12582912.0f                 // 1.5 * 2^23: round-to-nearest-even

// Orthonormal 8-pt DCT-II butterfly constants (double-derived)
#define CA  0.35355339059327373f
#define CB1 0.46193976625564337f
#define CB3 0.19134171618254492f
#define CD1 0.49039264020161522f
#define CD3 0.41573480615127262f
#define CD5 0.27778511650980114f
#define CD7 0.09754516100806413f

#define FDCT8(x0,x1,x2,x3,x4,x5,x6,x7) do {                                  \
    float e0=(x0)+(x7), e1=(x1)+(x6), e2=(x2)+(x5), e3=(x3)+(x4);            \
    float o0=(x0)-(x7), o1=(x1)-(x6), o2=(x2)-(x5), o3=(x3)-(x4);            \
    float ee0=e0+e3, ee1=e1+e2, eo0=e0-e3, eo1=e1-e2;                        \
    (x0) = CA*(ee0+ee1);                                                     \
    (x4) = CA*(ee0-ee1);                                                     \
    (x2) = CB1*eo0 + CB3*eo1;                                                \
    (x6) = CB3*eo0 - CB1*eo1;                                                \
    (x1) = CD1*o0 + CD3*o1 + CD5*o2 + CD7*o3;                                \
    (x3) = CD3*o0 - CD7*o1 - CD1*o2 - CD5*o3;                                \
    (x5) = CD5*o0 - CD1*o1 + CD7*o2 + CD3*o3;                                \
    (x7) = CD7*o0 - CD5*o1 + CD3*o2 - CD1*o3;                                \
} while(0)

#define IDCT8(x0,x1,x2,x3,x4,x5,x6,x7) do {                                  \
    float ee0 = CA*((x0)+(x4)), ee1 = CA*((x0)-(x4));                        \
    float eo0 = CB1*(x2) + CB3*(x6), eo1 = CB3*(x2) - CB1*(x6);              \
    float o0 = CD1*(x1) + CD3*(x3) + CD5*(x5) + CD7*(x7);                    \
    float o1 = CD3*(x1) - CD7*(x3) - CD1*(x5) - CD5*(x7);                    \
    float o2 = CD5*(x1) - CD1*(x3) + CD7*(x5) + CD3*(x7);                    \
    float o3 = CD7*(x1) - CD5*(x3) + CD3*(x5) - CD1*(x7);                    \
    float e0=ee0+eo0, e3=ee0-eo0, e1=ee1+eo1, e2=ee1-eo1;                    \
    (x0)=e0+o0; (x7)=e0-o0; (x1)=e1+o1; (x6)=e1-o1;                          \
    (x2)=e2+o2; (x5)=e2-o2; (x3)=e3+o3; (x4)=e3-o3;                          \
} while(0)

__constant__ float c_lum[64] = {
    16, 11, 10, 16, 24, 40, 51, 61,
    12, 12, 14, 19, 26, 58, 60, 55,
    14, 13, 16, 24, 40, 57, 69, 56,
    14, 17, 22, 29, 51, 87, 80, 62,
    18, 22, 37, 56, 68, 109, 103, 77,
    24, 35, 55, 64, 81, 104, 113, 92,
    49, 64, 78, 87, 103, 121, 120, 101,
    72, 92, 95, 98, 112, 100, 103, 99
};
__constant__ float c_chrom[64] = {
    17, 18, 24, 47, 99, 99, 99, 99,
    18, 21, 26, 66, 99, 99, 99, 99,
    24, 26, 56, 99, 99, 99, 99, 99,
    47, 66, 99, 99, 99, 99, 99, 99,
    99, 99, 99, 99, 99, 99, 99, 99,
    99, 99, 99, 99, 99, 99, 99, 99,
    99, 99, 99, 99, 99, 99, 99, 99,
    99, 99, 99, 99, 99, 99, 99, 99
};

__global__ void __launch_bounds__(NTHREADS, 2)
jpeg_kernel(const float* __restrict__ img,
            const int* __restrict__ quality,
            float* __restrict__ out)
{
    extern __shared__ float sm[];
    // zipped quant tables: entry (l, kp) at float4 index l*5+kp (pad breaks
    // the 128B-stride bank aliasing of the natural l*4 layout)
    __shared__ __align__(16) float qzipL[160];   // 8 l * 5 * float4
    __shared__ __align__(16) float qzipC[160];

    const int tid = threadIdx.x;

    // init: 2 tables * 8 l * 4 kp * 4 comps = 256 scalars
    if (tid < 256) {
        int t = tid >> 7;                 // 0 lum, 1 chrom
        int rem = tid & 127;
        int l = rem >> 4;
        int kp = (rem >> 2) & 3;
        int comp = rem & 3;               // 0:q0 1:r0 2:q1 3:r1
        int k = 2 * kp + (comp >> 1);
        int q = *quality;
        q = max(1, min(100, q));
        float scale = (q < 50) ? (5000.0f / (float)q) : (200.0f - 2.0f * (float)q);
        float base = t ? c_chrom[k * 8 + l] : c_lum[k * 8 + l];
        float v = (base * scale + 50.0f) / 100.0f;
        v = fminf(fmaxf(v, 1.0f), 255.0f);
        float outv = (comp & 1) ? (1.0f / v) : v;
        (t ? qzipC : qzipL)[(l * 5 + kp) * 4 + comp] = outv;
    }

    const int b = blockIdx.x >> 6;
    const int strip = blockIdx.x & 63;
    const int row0 = strip * 8;
    const size_t CH = (size_t)IMG_H * IMG_W;
    const size_t img_base = (size_t)b * 3 * CH;

    // ---- Phase A: load + RGB->YCbCr (x255 folded) into block-slot smem ----
    #pragma unroll
    for (int g = 0; g < 2; g++) {
        int idx = tid + g * NTHREADS;
        if (idx < 1024) {
            int r = idx >> 7;
            int col = (idx & 127) << 2;
            size_t off = img_base + (size_t)(row0 + r) * IMG_W + col;
            float4 r4 = *(const float4*)(img + off);
            float4 g4 = *(const float4*)(img + off + CH);
            float4 b4 = *(const float4*)(img + off + 2 * CH);
            float4 y4, cb4, cr4;
            {
                const float* Rp = &r4.x; const float* Gp = &g4.x; const float* Bp = &b4.x;
                float* Yp = &y4.x; float* Cbp = &cb4.x; float* Crp = &cr4.x;
                #pragma unroll
                for (int j = 0; j < 4; j++) {
                    float R = Rp[j], G = Gp[j], B = Bp[j];
                    Yp[j]  = fmaf(76.245f, R, fmaf(149.685f, G, 29.07f * B));
                    Cbp[j] = fmaf(-43.0185f, R, fmaf(-84.4815f, G, fmaf(127.5f, B, 128.0f)));
                    Crp[j] = fmaf(127.5f, R, fmaf(-106.7685f, G, fmaf(-20.7315f, B, 128.0f)));
                }
            }
            int blk = col >> 3;
            int sb = blk * 72 + (r >> 2) * 36 + (r & 3) * 8 + (col & 7);
            *(float4*)(sm + sb)             = y4;
            *(float4*)(sm + 64 * 72 + sb)   = cb4;
            *(float4*)(sm + 128 * 72 + sb)  = cr4;
        }
    }
    __syncthreads();

    // ---- Phase B: thread quad per 8x8 block (2 rows / 2 cols each) ----
    {
        const int unit = tid >> 2;          // 0..191 (c*64 + blk)
        const int q = tid & 3;              // row-pair index
        const int c = unit >> 6;
        float* ub = sm + unit * 72;

        float x[2][8];
        // load my 2 spatial rows (a = 2q, 2q+1)
        #pragma unroll
        for (int i = 0; i < 2; i++) {
            int a = 2 * q + i;
            float* rp = ub + (a >> 2) * 36 + (a & 3) * 8;
            float4 v0 = *(const float4*)(rp);
            float4 v1 = *(const float4*)(rp + 4);
            x[i][0]=v0.x; x[i][1]=v0.y; x[i][2]=v0.z; x[i][3]=v0.w;
            x[i][4]=v1.x; x[i][5]=v1.y; x[i][6]=v1.z; x[i][7]=v1.w;
        }
        // row forward DCT
        #pragma unroll
        for (int i = 0; i < 2; i++)
            FDCT8(x[i][0],x[i][1],x[i][2],x[i][3],x[i][4],x[i][5],x[i][6],x[i][7]);

        __syncwarp();
        // transpose store T1[l][r]: my r's (2q,2q+1) are one float2
        #pragma unroll
        for (int l = 0; l < 8; l++) {
            *(float2*)(ub + (l >> 2) * 36 + (l & 3) * 8 + 2 * q)
                = make_float2(x[0][l], x[1][l]);
        }
        __syncwarp();

        // load my 2 transposed rows (cols l = 2q, 2q+1), contiguous over r
        float y[2][8];
        #pragma unroll
        for (int j = 0; j < 2; j++) {
            int l = 2 * q + j;
            float* rp = ub + (l >> 2) * 36 + (l & 3) * 8;
            float4 v0 = *(const float4*)(rp);
            float4 v1 = *(const float4*)(rp + 4);
            y[j][0]=v0.x; y[j][1]=v0.y; y[j][2]=v0.z; y[j][3]=v0.w;
            y[j][4]=v1.x; y[j][5]=v1.y; y[j][6]=v1.z; y[j][7]=v1.w;
        }
        // column forward DCT -> y[j][k] = D[k][2q+j]
        #pragma unroll
        for (int j = 0; j < 2; j++)
            FDCT8(y[j][0],y[j][1],y[j][2],y[j][3],y[j][4],y[j][5],y[j][6],y[j][7]);

        // -128 input shift commutes to DC only (owner: q=0, j=0, k=0)
        if (q == 0) y[0][0] -= 1024.0f;

        // quantize: zipped (q0,r0,q1,r1) LDS.128 + fmaf magic round-to-even
        {
            const float* qz = ((b * 3 + c) < BATCH) ? qzipL : qzipC;
            #pragma unroll
            for (int j = 0; j < 2; j++) {
                int l = 2 * q + j;
                const float4* zl = (const float4*)(qz + l * 20);  // (l*5)*4
                #pragma unroll
                for (int kp = 0; kp < 4; kp++) {
                    float4 z = zl[kp];
                    float t0 = fmaf(y[j][2*kp],   z.y, MAGIC);
                    float t1 = fmaf(y[j][2*kp+1], z.w, MAGIC);
                    t0 = __fadd_rn(t0, -MAGIC);
                    t1 = __fadd_rn(t1, -MAGIC);
                    y[j][2*kp]   = t0 * z.x;
                    y[j][2*kp+1] = t1 * z.z;
                }
            }
        }

        // +128 output shift commutes to DC
        if (q == 0) y[0][0] += 1024.0f;

        // column inverse DCT -> y[j][i] = T2[i][2q+j]
        #pragma unroll
        for (int j = 0; j < 2; j++)
            IDCT8(y[j][0],y[j][1],y[j][2],y[j][3],y[j][4],y[j][5],y[j][6],y[j][7]);

        __syncwarp();   // all lanes done reading T1 before overwriting with T2
        // store T2[i][l']: my l's (2q,2q+1) are one float2 per row i
        #pragma unroll
        for (int i = 0; i < 8; i++) {
            *(float2*)(ub + (i >> 2) * 36 + (i & 3) * 8 + 2 * q)
                = make_float2(y[0][i], y[1][i]);
        }
        __syncwarp();

        // load my 2 rows of T2, row inverse DCT -> spatial pixels
        #pragma unroll
        for (int i = 0; i < 2; i++) {
            int a = 2 * q + i;
            float* rp = ub + (a >> 2) * 36 + (a & 3) * 8;
            float4 v0 = *(const float4*)(rp);
            float4 v1 = *(const float4*)(rp + 4);
            x[i][0]=v0.x; x[i][1]=v0.y; x[i][2]=v0.z; x[i][3]=v0.w;
            x[i][4]=v1.x; x[i][5]=v1.y; x[i][6]=v1.z; x[i][7]=v1.w;
        }
        #pragma unroll
        for (int i = 0; i < 2; i++)
            IDCT8(x[i][0],x[i][1],x[i][2],x[i][3],x[i][4],x[i][5],x[i][6],x[i][7]);

        // pixel store targets exactly the T2 rows only THIS lane read -> no hazard
        #pragma unroll
        for (int i = 0; i < 2; i++) {
            int a = 2 * q + i;
            float* rp = ub + (a >> 2) * 36 + (a & 3) * 8;
            *(float4*)(rp)     = make_float4(x[i][0],x[i][1],x[i][2],x[i][3]);
            *(float4*)(rp + 4) = make_float4(x[i][4],x[i][5],x[i][6],x[i][7]);
        }
    }
    __syncthreads();

    // ---- Phase C: YCbCr->RGB, clip, store ----
    #pragma unroll
    for (int g = 0; g < 2; g++) {
        int idx = tid + g * NTHREADS;
        if (idx < 1024) {
            int r = idx >> 7;
            int col = (idx & 127) << 2;
            int blk = col >> 3;
            int sb = blk * 72 + (r >> 2) * 36 + (r & 3) * 8 + (col & 7);
            float4 y4  = *(const float4*)(sm + sb);
            float4 cb4 = *(const float4*)(sm + 64 * 72 + sb);
            float4 cr4 = *(const float4*)(sm + 128 * 72 + sb);
            float4 ro, go, bo;
            {
                const float* Yp = &y4.x; const float* Cbp = &cb4.x; const float* Crp = &cr4.x;
                float* Rp = &ro.x; float* Gp = &go.x; float* Bp = &bo.x;
                #pragma unroll
                for (int j = 0; j < 4; j++) {
                    float y  = Yp[j];
                    float cb = Cbp[j] - 128.0f;
                    float cr = Crp[j] - 128.0f;
                    float rr = y + 1.402f * cr;
                    float gg = y - 0.34414f * cb - 0.71414f * cr;
                    float bb = y + 1.772f * cb;
                    Rp[j] = fminf(fmaxf(rr * (1.0f / 255.0f), 0.0f), 1.0f);
                    Gp[j] = fminf(fmaxf(gg * (1.0f / 255.0f), 0.0f), 1.0f);
                    Bp[j] = fminf(fmaxf(bb * (1.0f / 255.0f), 0.0f), 1.0f);
                }
            }
            size_t off = img_base + (size_t)(row0 + r) * IMG_W + col;
            *(float4*)(out + off)          = ro;
            *(float4*)(out + off + CH)     = go;
            *(float4*)(out + off + 2 * CH) = bo;
        }
    }
}

extern "C" void kernel_launch(void* const* d_in, const int* in_sizes, int n_in,
                              void* d_out, int out_size)
{
    const float* img = (const float*)d_in[0];
    const int* quality = (const int*)d_in[1];
    float* out = (float*)d_out;

    cudaFuncSetAttribute(jpeg_kernel,
                         cudaFuncAttributeMaxDynamicSharedMemorySize,
                         SMEM_BYTES);

    dim3 grid(BATCH * (IMG_H / 8));  // 1024 CTAs
    jpeg_kernel<<<grid, NTHREADS, SMEM_BYTES>>>(img, quality, out);
}